// round 1
// baseline (speedup 1.0000x reference)
#include <cuda_runtime.h>
#include <math.h>

// Problem constants
#define BATCH   4
#define TSEQ    2048
#define NHEAD   16
#define HSIZE   64
#define CEMB    1024        // NHEAD*HSIZE
#define MROWS   (BATCH*TSEQ)   // 8192

// Scratch (device globals: allocation-free rule)
__device__ float g_q[(size_t)BATCH * NHEAD * TSEQ * HSIZE];   // [B,H,T,D], pre-scaled by D^-0.5
__device__ float g_k[(size_t)BATCH * NHEAD * TSEQ * HSIZE];
__device__ float g_v[(size_t)BATCH * NHEAD * TSEQ * HSIZE];
__device__ float g_attn[(size_t)MROWS * CEMB];                // [B*T, C]

// ---------------------------------------------------------------------------
// 128x128x8 fp32 GEMM, 256 threads, 8x8 per-thread microtile.
// mode 0: C unused; scatter output into g_q/g_k/g_v [B,H,T,D] (QKV epilogue),
//         q pre-scaled by 0.125 = HSIZE^-0.5.
// mode 1: C[m*N+n] = acc + bias[n]   (projection epilogue)
// M,N,K all multiples of 128/8 here -> no bounds checks.
// ---------------------------------------------------------------------------
__global__ __launch_bounds__(256) void gemm_kernel(
    const float* __restrict__ A, const float* __restrict__ B,
    const float* __restrict__ bias, float* __restrict__ C,
    int M, int N, int K, int mode)
{
    __shared__ float As[8][128];
    __shared__ float Bs[8][132];

    const int tid = threadIdx.x;
    const int tx = tid & 15;          // 0..15 -> column group
    const int ty = tid >> 4;          // 0..15 -> row group
    const int m0 = blockIdx.y * 128;
    const int n0 = blockIdx.x * 128;

    // A tile load: thread -> (row am, 4 k's starting at ak)
    const int am = tid >> 1;
    const int ak = (tid & 1) * 4;
    // B tile load: thread -> (k row bk, 4 n's starting at bn)
    const int bk = tid >> 5;
    const int bn = (tid & 31) * 4;

    const float* Ap = A + (size_t)(m0 + am) * K + ak;
    const float* Bp = B + (size_t)bk * N + n0 + bn;

    float acc[8][8];
#pragma unroll
    for (int i = 0; i < 8; ++i)
#pragma unroll
        for (int j = 0; j < 8; ++j) acc[i][j] = 0.f;

    for (int k0 = 0; k0 < K; k0 += 8) {
        float4 av = *(const float4*)(Ap + k0);
        float4 bv = *(const float4*)(Bp + (size_t)k0 * N);
        As[ak + 0][am] = av.x;
        As[ak + 1][am] = av.y;
        As[ak + 2][am] = av.z;
        As[ak + 3][am] = av.w;
        *(float4*)&Bs[bk][bn] = bv;
        __syncthreads();

#pragma unroll
        for (int kk = 0; kk < 8; ++kk) {
            float4 a0 = *(const float4*)&As[kk][ty * 8];
            float4 a1 = *(const float4*)&As[kk][ty * 8 + 4];
            float4 b0 = *(const float4*)&Bs[kk][tx * 8];
            float4 b1 = *(const float4*)&Bs[kk][tx * 8 + 4];
            float a[8] = {a0.x, a0.y, a0.z, a0.w, a1.x, a1.y, a1.z, a1.w};
            float b[8] = {b0.x, b0.y, b0.z, b0.w, b1.x, b1.y, b1.z, b1.w};
#pragma unroll
            for (int i = 0; i < 8; ++i)
#pragma unroll
                for (int j = 0; j < 8; ++j)
                    acc[i][j] = fmaf(a[i], b[j], acc[i][j]);
        }
        __syncthreads();
    }

    if (mode == 0) {
        // QKV scatter epilogue -> [B,H,T,D]
#pragma unroll
        for (int i = 0; i < 8; ++i) {
            int m = m0 + ty * 8 + i;
            int bb = m >> 11;               // m / TSEQ
            int t  = m & (TSEQ - 1);
#pragma unroll
            for (int j = 0; j < 8; ++j) {
                int n = n0 + tx * 8 + j;
                int which = n >> 10;        // 0=q,1=k,2=v
                int cc = n & 1023;
                int h = cc >> 6;
                int d = cc & 63;
                size_t dst = (((size_t)(bb * NHEAD + h) * TSEQ) + t) * HSIZE + d;
                float v = acc[i][j];
                if (which == 0)      g_q[dst] = v * 0.125f;   // fold D^-0.5
                else if (which == 1) g_k[dst] = v;
                else                 g_v[dst] = v;
            }
        }
    } else {
#pragma unroll
        for (int i = 0; i < 8; ++i) {
            int m = m0 + ty * 8 + i;
#pragma unroll
            for (int j = 0; j < 8; ++j) {
                int n = n0 + tx * 8 + j;
                C[(size_t)m * N + n] = acc[i][j] + bias[n];
            }
        }
    }
}

// ---------------------------------------------------------------------------
// Causal flash attention, fp32. One thread = one query row (D=64 in regs).
// Block = 128 threads = 128 query rows; K/V tiles (64x64) staged in smem and
// read via broadcast LDS. Online softmax with per-tile rescale.
// Grid: (T/128, B*H). g_q already carries the D^-0.5 scale.
// ---------------------------------------------------------------------------
__global__ __launch_bounds__(128) void attn_kernel()
{
    __shared__ float Ks[64][64];
    __shared__ float Vs[64][64];

    const int tid = threadIdx.x;
    const int bh  = blockIdx.y;          // 0..B*H-1
    const int qb  = blockIdx.x;          // 0..T/128-1
    const int q   = qb * 128 + tid;

    const float* Qr = g_q + ((size_t)bh * TSEQ + q) * HSIZE;
    float qr[64];
#pragma unroll
    for (int d = 0; d < 64; d += 4) {
        float4 v = *(const float4*)(Qr + d);
        qr[d] = v.x; qr[d + 1] = v.y; qr[d + 2] = v.z; qr[d + 3] = v.w;
    }

    float o[64];
#pragma unroll
    for (int d = 0; d < 64; ++d) o[d] = 0.f;
    float mrow = -INFINITY;
    float lrow = 0.f;

    const int ntiles = qb * 2 + 2;       // 64-key tiles covering [0, q0+128)
    for (int kt = 0; kt < ntiles; ++kt) {
        const float4* Kg = (const float4*)(g_k + ((size_t)bh * TSEQ + kt * 64) * HSIZE);
        const float4* Vg = (const float4*)(g_v + ((size_t)bh * TSEQ + kt * 64) * HSIZE);
        float4* Ks4 = (float4*)&Ks[0][0];
        float4* Vs4 = (float4*)&Vs[0][0];
#pragma unroll
        for (int r = 0; r < 8; ++r) {
            int f = tid + r * 128;       // 1024 float4 per tile
            Ks4[f] = Kg[f];
            Vs4[f] = Vg[f];
        }
        __syncthreads();

        int kmax = q - kt * 64;          // valid keys: j in [0, min(63,kmax)]
        if (kmax >= 0) {
            if (kmax > 63) kmax = 63;
            float s[64];
            float tmax = -INFINITY;
#pragma unroll
            for (int j = 0; j < 64; ++j) {
                if (j <= kmax) {
                    float a0 = 0.f, a1 = 0.f, a2 = 0.f, a3 = 0.f;
#pragma unroll
                    for (int d = 0; d < 64; d += 4) {
                        a0 = fmaf(qr[d],     Ks[j][d],     a0);
                        a1 = fmaf(qr[d + 1], Ks[j][d + 1], a1);
                        a2 = fmaf(qr[d + 2], Ks[j][d + 2], a2);
                        a3 = fmaf(qr[d + 3], Ks[j][d + 3], a3);
                    }
                    s[j] = (a0 + a1) + (a2 + a3);
                    tmax = fmaxf(tmax, s[j]);
                }
            }
            float newm = fmaxf(mrow, tmax);
            float corr = __expf(mrow - newm);    // exp(-inf)=0 on first tile
            lrow *= corr;
#pragma unroll
            for (int d = 0; d < 64; ++d) o[d] *= corr;
#pragma unroll
            for (int j = 0; j < 64; ++j) {
                if (j <= kmax) {
                    float p = __expf(s[j] - newm);
                    lrow += p;
#pragma unroll
                    for (int d = 0; d < 64; ++d)
                        o[d] = fmaf(p, Vs[j][d], o[d]);
                }
            }
            mrow = newm;
        }
        __syncthreads();
    }

    const int b = bh >> 4;
    const int h = bh & 15;
    const float inv = 1.f / lrow;
    float* Out = g_attn + ((size_t)(b * TSEQ + q)) * CEMB + h * HSIZE;
#pragma unroll
    for (int d = 0; d < 64; d += 4) {
        float4 v;
        v.x = o[d] * inv; v.y = o[d + 1] * inv;
        v.z = o[d + 2] * inv; v.w = o[d + 3] * inv;
        *(float4*)(Out + d) = v;
    }
}

// ---------------------------------------------------------------------------
extern "C" void kernel_launch(void* const* d_in, const int* in_sizes, int n_in,
                              void* d_out, int out_size)
{
    const float* x      = (const float*)d_in[0];   // [B,T,C]
    const float* w_qkv  = (const float*)d_in[1];   // [C, 3C]
    const float* w_proj = (const float*)d_in[2];   // [C, C]
    const float* b_proj = (const float*)d_in[3];   // [C]
    float* out = (float*)d_out;                    // [B,T,C]

    float* attn_ptr = nullptr;
    cudaGetSymbolAddress((void**)&attn_ptr, g_attn);

    // 1) QKV GEMM + head-major scatter
    gemm_kernel<<<dim3(3 * CEMB / 128, MROWS / 128), 256>>>(
        x, w_qkv, nullptr, nullptr, MROWS, 3 * CEMB, CEMB, 0);

    // 2) Causal flash attention
    attn_kernel<<<dim3(TSEQ / 128, BATCH * NHEAD), 128>>>();

    // 3) Output projection + bias
    gemm_kernel<<<dim3(CEMB / 128, MROWS / 128), 256>>>(
        attn_ptr, w_proj, b_proj, out, MROWS, CEMB, CEMB, 1);
}

// round 3
// speedup vs baseline: 1.4067x; 1.4067x over previous
#include <cuda_runtime.h>
#include <math.h>
#include <stdint.h>

// Problem constants
#define BATCH   4
#define TSEQ    2048
#define NHEAD   16
#define HSIZE   64
#define CEMB    1024
#define MROWS   (BATCH*TSEQ)   // 8192

// Scratch (device globals: allocation-free rule)
__device__ float g_q[(size_t)BATCH * NHEAD * TSEQ * HSIZE];   // [B,H,T,D], q pre-scaled
__device__ float g_k[(size_t)BATCH * NHEAD * TSEQ * HSIZE];
__device__ float g_v[(size_t)BATCH * NHEAD * TSEQ * HSIZE];
__device__ float g_attn[(size_t)MROWS * CEMB];                // [B*T, C]
__device__ float g_wt_qkv[(size_t)3 * CEMB * CEMB];           // [3C, C] K-major
__device__ float g_wt_proj[(size_t)CEMB * CEMB];              // [C, C]  K-major

// ---------------------------------------------------------------------------
// tf32 helpers (legacy mma.sync path — valid on plain sm_103 PTX target)
// ---------------------------------------------------------------------------
__device__ __forceinline__ uint32_t f2tf32(float x) {
    uint32_t r;
    asm("cvt.rna.tf32.f32 %0, %1;" : "=r"(r) : "f"(x));
    return r;
}
__device__ __forceinline__ void mma_tf32(float& c0, float& c1, float& c2, float& c3,
                                         uint32_t a0, uint32_t a1, uint32_t a2, uint32_t a3,
                                         uint32_t b0, uint32_t b1) {
    asm volatile("mma.sync.aligned.m16n8k8.row.col.f32.tf32.tf32.f32 "
                 "{%0,%1,%2,%3}, {%4,%5,%6,%7}, {%8,%9}, {%0,%1,%2,%3};"
                 : "+f"(c0), "+f"(c1), "+f"(c2), "+f"(c3)
                 : "r"(a0), "r"(a1), "r"(a2), "r"(a3), "r"(b0), "r"(b1));
}

// ---------------------------------------------------------------------------
// Weight transpose: in [R][C] row-major -> out [C][R] row-major (K-major weights)
// ---------------------------------------------------------------------------
__global__ __launch_bounds__(256) void transpose_k(const float* __restrict__ in,
                                                   float* __restrict__ out, int R, int C)
{
    __shared__ float t[32][33];
    int bx = blockIdx.x * 32, by = blockIdx.y * 32;
#pragma unroll
    for (int i = 0; i < 32; i += 8)
        t[threadIdx.y + i][threadIdx.x] = in[(size_t)(by + threadIdx.y + i) * C + bx + threadIdx.x];
    __syncthreads();
#pragma unroll
    for (int i = 0; i < 32; i += 8)
        out[(size_t)(bx + threadIdx.y + i) * R + by + threadIdx.x] = t[threadIdx.x][threadIdx.y + i];
}

// ---------------------------------------------------------------------------
// tf32 tensor-core GEMM via mma.sync m16n8k8.
// C[M,N] = A[M,K] * Bt[N,K]^T (+bias). Block 256 thr (8 warps), tile 128x128.
// Warp grid 4(m) x 2(n): warp computes 32x64 = 2(m16) x 8(n8) mma tiles.
// K staged in 32-wide smem chunks: As[128][36], Bs[128][36] (pad 36 => frag LDS
// bank = 4*group + tig : conflict-free).
// mode 0: scatter into g_q/g_k/g_v [B,H,T,D] (q scaled 0.125); mode 1: C=acc+bias.
// ---------------------------------------------------------------------------
__global__ __launch_bounds__(256) void gemm_mma(
    const float* __restrict__ A, const float* __restrict__ Bt,
    const float* __restrict__ bias, float* __restrict__ C,
    int M, int N, int K, int mode)
{
    __shared__ float As[128][36];
    __shared__ float Bs[128][36];

    const int tid  = threadIdx.x;
    const int wid  = tid >> 5;
    const int lane = tid & 31;
    const int g    = lane >> 2;       // groupID 0..7
    const int t    = lane & 3;        // threadID_in_group 0..3
    const int wm   = wid & 3;         // warp row 0..3  -> 32 rows each
    const int wn   = wid >> 2;        // warp col 0..1  -> 64 cols each
    const int m0 = blockIdx.y * 128;
    const int n0 = blockIdx.x * 128;

    // loader mapping: f = tid + i*256 ; row r = f>>3 (0..127), kquad kq = f&7
    const int lr = tid >> 3;
    const int lk = (tid & 7) * 4;

    float c[2][8][4];
#pragma unroll
    for (int mt = 0; mt < 2; ++mt)
#pragma unroll
        for (int nt = 0; nt < 8; ++nt)
#pragma unroll
            for (int j = 0; j < 4; ++j) c[mt][nt][j] = 0.f;

    for (int k0 = 0; k0 < K; k0 += 32) {
        // stage A and B chunks (convert to tf32 bits on the way in)
#pragma unroll
        for (int i = 0; i < 4; ++i) {
            int r = lr + i * 32;
            float4 av = *(const float4*)(A + (size_t)(m0 + r) * K + k0 + lk);
            float4 bv = *(const float4*)(Bt + (size_t)(n0 + r) * K + k0 + lk);
            float4 ac, bc;
            ac.x = __uint_as_float(f2tf32(av.x)); ac.y = __uint_as_float(f2tf32(av.y));
            ac.z = __uint_as_float(f2tf32(av.z)); ac.w = __uint_as_float(f2tf32(av.w));
            bc.x = __uint_as_float(f2tf32(bv.x)); bc.y = __uint_as_float(f2tf32(bv.y));
            bc.z = __uint_as_float(f2tf32(bv.z)); bc.w = __uint_as_float(f2tf32(bv.w));
            *(float4*)&As[r][lk] = ac;
            *(float4*)&Bs[r][lk] = bc;
        }
        __syncthreads();

#pragma unroll
        for (int kt = 0; kt < 4; ++kt) {
            const int kb = kt * 8;
            // B fragments: b0 at (k=tig, n=g), b1 at (k=tig+4, n=g)
            uint32_t bf[8][2];
#pragma unroll
            for (int nt = 0; nt < 8; ++nt) {
                int n = wn * 64 + nt * 8 + g;
                bf[nt][0] = __float_as_uint(Bs[n][kb + t]);
                bf[nt][1] = __float_as_uint(Bs[n][kb + t + 4]);
            }
#pragma unroll
            for (int mt = 0; mt < 2; ++mt) {
                int mb = wm * 32 + mt * 16;
                uint32_t a0 = __float_as_uint(As[mb + g][kb + t]);
                uint32_t a1 = __float_as_uint(As[mb + g + 8][kb + t]);
                uint32_t a2 = __float_as_uint(As[mb + g][kb + t + 4]);
                uint32_t a3 = __float_as_uint(As[mb + g + 8][kb + t + 4]);
#pragma unroll
                for (int nt = 0; nt < 8; ++nt)
                    mma_tf32(c[mt][nt][0], c[mt][nt][1], c[mt][nt][2], c[mt][nt][3],
                             a0, a1, a2, a3, bf[nt][0], bf[nt][1]);
            }
        }
        __syncthreads();
    }

    // Epilogue. c0,c1 -> (row = base+g, cols 2t,2t+1); c2,c3 -> row+8.
    const int nbase = n0 + wn * 64;       // 64-aligned -> single (which,head) region
    if (mode == 0) {
        const int which = nbase >> 10;
        const int h = (nbase & 1023) >> 6;
        const float sc = (which == 0) ? 0.125f : 1.0f;
        float* base = (which == 0 ? g_q : (which == 1 ? g_k : g_v));
#pragma unroll
        for (int mt = 0; mt < 2; ++mt) {
            int r0 = m0 + wm * 32 + mt * 16 + g;
            int bb0 = r0 >> 11, tt0 = r0 & (TSEQ - 1);
            int r1 = r0 + 8;
            int bb1 = r1 >> 11, tt1 = r1 & (TSEQ - 1);
            float* d0 = base + (((size_t)(bb0 * NHEAD + h) * TSEQ) + tt0) * HSIZE;
            float* d1 = base + (((size_t)(bb1 * NHEAD + h) * TSEQ) + tt1) * HSIZE;
#pragma unroll
            for (int nt = 0; nt < 8; ++nt) {
                int d = nt * 8 + 2 * t;
                float2 v0 = {c[mt][nt][0] * sc, c[mt][nt][1] * sc};
                float2 v1 = {c[mt][nt][2] * sc, c[mt][nt][3] * sc};
                *(float2*)(d0 + d) = v0;
                *(float2*)(d1 + d) = v1;
            }
        }
    } else {
#pragma unroll
        for (int mt = 0; mt < 2; ++mt) {
            int r0 = m0 + wm * 32 + mt * 16 + g;
#pragma unroll
            for (int nt = 0; nt < 8; ++nt) {
                int n = nbase + nt * 8 + 2 * t;
                float2 bv = *(const float2*)(bias + n);
                float2 v0 = {c[mt][nt][0] + bv.x, c[mt][nt][1] + bv.y};
                float2 v1 = {c[mt][nt][2] + bv.x, c[mt][nt][3] + bv.y};
                *(float2*)(C + (size_t)r0 * N + n) = v0;
                *(float2*)(C + (size_t)(r0 + 8) * N + n) = v1;
            }
        }
    }
}

// ---------------------------------------------------------------------------
// Causal flash attention, fp32 (unchanged — known correct).
// ---------------------------------------------------------------------------
__global__ __launch_bounds__(128) void attn_kernel()
{
    __shared__ float Ks[64][64];
    __shared__ float Vs[64][64];

    const int tid = threadIdx.x;
    const int bh  = blockIdx.y;
    const int qb  = blockIdx.x;
    const int q   = qb * 128 + tid;

    const float* Qr = g_q + ((size_t)bh * TSEQ + q) * HSIZE;
    float qr[64];
#pragma unroll
    for (int d = 0; d < 64; d += 4) {
        float4 v = *(const float4*)(Qr + d);
        qr[d] = v.x; qr[d + 1] = v.y; qr[d + 2] = v.z; qr[d + 3] = v.w;
    }

    float o[64];
#pragma unroll
    for (int d = 0; d < 64; ++d) o[d] = 0.f;
    float mrow = -INFINITY;
    float lrow = 0.f;

    const int ntiles = qb * 2 + 2;
    for (int kt = 0; kt < ntiles; ++kt) {
        const float4* Kg = (const float4*)(g_k + ((size_t)bh * TSEQ + kt * 64) * HSIZE);
        const float4* Vg = (const float4*)(g_v + ((size_t)bh * TSEQ + kt * 64) * HSIZE);
        float4* Ks4 = (float4*)&Ks[0][0];
        float4* Vs4 = (float4*)&Vs[0][0];
#pragma unroll
        for (int r = 0; r < 8; ++r) {
            int f = tid + r * 128;
            Ks4[f] = Kg[f];
            Vs4[f] = Vg[f];
        }
        __syncthreads();

        int kmax = q - kt * 64;
        if (kmax >= 0) {
            if (kmax > 63) kmax = 63;
            float s[64];
            float tmax = -INFINITY;
#pragma unroll
            for (int j = 0; j < 64; ++j) {
                if (j <= kmax) {
                    float a0 = 0.f, a1 = 0.f, a2 = 0.f, a3 = 0.f;
#pragma unroll
                    for (int d = 0; d < 64; d += 4) {
                        a0 = fmaf(qr[d],     Ks[j][d],     a0);
                        a1 = fmaf(qr[d + 1], Ks[j][d + 1], a1);
                        a2 = fmaf(qr[d + 2], Ks[j][d + 2], a2);
                        a3 = fmaf(qr[d + 3], Ks[j][d + 3], a3);
                    }
                    s[j] = (a0 + a1) + (a2 + a3);
                    tmax = fmaxf(tmax, s[j]);
                }
            }
            float newm = fmaxf(mrow, tmax);
            float corr = __expf(mrow - newm);
            lrow *= corr;
#pragma unroll
            for (int d = 0; d < 64; ++d) o[d] *= corr;
#pragma unroll
            for (int j = 0; j < 64; ++j) {
                if (j <= kmax) {
                    float p = __expf(s[j] - newm);
                    lrow += p;
#pragma unroll
                    for (int d = 0; d < 64; ++d)
                        o[d] = fmaf(p, Vs[j][d], o[d]);
                }
            }
            mrow = newm;
        }
        __syncthreads();
    }

    const int b = bh >> 4;
    const int h = bh & 15;
    const float inv = 1.f / lrow;
    float* Out = g_attn + ((size_t)(b * TSEQ + q)) * CEMB + h * HSIZE;
#pragma unroll
    for (int d = 0; d < 64; d += 4) {
        float4 v;
        v.x = o[d] * inv; v.y = o[d + 1] * inv;
        v.z = o[d + 2] * inv; v.w = o[d + 3] * inv;
        *(float4*)(Out + d) = v;
    }
}

// ---------------------------------------------------------------------------
extern "C" void kernel_launch(void* const* d_in, const int* in_sizes, int n_in,
                              void* d_out, int out_size)
{
    const float* x      = (const float*)d_in[0];   // [B,T,C]
    const float* w_qkv  = (const float*)d_in[1];   // [C, 3C]
    const float* w_proj = (const float*)d_in[2];   // [C, C]
    const float* b_proj = (const float*)d_in[3];   // [C]
    float* out = (float*)d_out;                    // [B,T,C]

    float *attn_ptr = nullptr, *wtq = nullptr, *wtp = nullptr;
    cudaGetSymbolAddress((void**)&attn_ptr, g_attn);
    cudaGetSymbolAddress((void**)&wtq, g_wt_qkv);
    cudaGetSymbolAddress((void**)&wtp, g_wt_proj);

    // 0) transpose weights to K-major
    transpose_k<<<dim3(3 * CEMB / 32, CEMB / 32), dim3(32, 8)>>>(w_qkv, wtq, CEMB, 3 * CEMB);
    transpose_k<<<dim3(CEMB / 32, CEMB / 32), dim3(32, 8)>>>(w_proj, wtp, CEMB, CEMB);

    // 1) QKV GEMM (tf32 mma) + head-major scatter
    gemm_mma<<<dim3(3 * CEMB / 128, MROWS / 128), 256>>>(
        x, wtq, nullptr, nullptr, MROWS, 3 * CEMB, CEMB, 0);

    // 2) Causal flash attention
    attn_kernel<<<dim3(TSEQ / 128, BATCH * NHEAD), 128>>>();

    // 3) Output projection + bias (tf32 mma)
    gemm_mma<<<dim3(CEMB / 128, MROWS / 128), 256>>>(
        attn_ptr, wtp, b_proj, out, MROWS, CEMB, CEMB, 1);
}

// round 4
// speedup vs baseline: 4.4546x; 3.1666x over previous
#include <cuda_runtime.h>
#include <math.h>
#include <stdint.h>

// Problem constants
#define BATCH   4
#define TSEQ    2048
#define NHEAD   16
#define HSIZE   64
#define CEMB    1024
#define MROWS   (BATCH*TSEQ)   // 8192

// Scratch (device globals: allocation-free rule)
__device__ float g_q[(size_t)BATCH * NHEAD * TSEQ * HSIZE];   // [B,H,T,D], q pre-scaled
__device__ float g_k[(size_t)BATCH * NHEAD * TSEQ * HSIZE];   // [B,H,T,D]
__device__ float g_v[(size_t)BATCH * NHEAD * TSEQ * HSIZE];   // [B,H,D,T]  (transposed!)
__device__ float g_attn[(size_t)MROWS * CEMB];                // [B*T, C]
__device__ float g_wt_qkv[(size_t)3 * CEMB * CEMB];           // [3C, C] K-major
__device__ float g_wt_proj[(size_t)CEMB * CEMB];              // [C, C]  K-major

// ---------------------------------------------------------------------------
// tf32 helpers (legacy mma.sync path — valid on plain sm_103 PTX target)
// ---------------------------------------------------------------------------
__device__ __forceinline__ uint32_t f2tf32(float x) {
    uint32_t r;
    asm("cvt.rna.tf32.f32 %0, %1;" : "=r"(r) : "f"(x));
    return r;
}
__device__ __forceinline__ void mma_tf32(float& c0, float& c1, float& c2, float& c3,
                                         uint32_t a0, uint32_t a1, uint32_t a2, uint32_t a3,
                                         uint32_t b0, uint32_t b1) {
    asm volatile("mma.sync.aligned.m16n8k8.row.col.f32.tf32.tf32.f32 "
                 "{%0,%1,%2,%3}, {%4,%5,%6,%7}, {%8,%9}, {%0,%1,%2,%3};"
                 : "+f"(c0), "+f"(c1), "+f"(c2), "+f"(c3)
                 : "r"(a0), "r"(a1), "r"(a2), "r"(a3), "r"(b0), "r"(b1));
}

// ---------------------------------------------------------------------------
// Weight transpose: in [R][C] row-major -> out [C][R] row-major (K-major weights)
// ---------------------------------------------------------------------------
__global__ __launch_bounds__(256) void transpose_k(const float* __restrict__ in,
                                                   float* __restrict__ out, int R, int C)
{
    __shared__ float t[32][33];
    int bx = blockIdx.x * 32, by = blockIdx.y * 32;
#pragma unroll
    for (int i = 0; i < 32; i += 8)
        t[threadIdx.y + i][threadIdx.x] = in[(size_t)(by + threadIdx.y + i) * C + bx + threadIdx.x];
    __syncthreads();
#pragma unroll
    for (int i = 0; i < 32; i += 8)
        out[(size_t)(bx + threadIdx.y + i) * R + by + threadIdx.x] = t[threadIdx.x][threadIdx.y + i];
}

// ---------------------------------------------------------------------------
// tf32 tensor-core GEMM via mma.sync m16n8k8 (unchanged structure from round 3).
// mode 0: scatter into g_q (scaled 0.125) / g_k [B,H,T,D]; g_v [B,H,D,T].
// mode 1: C = acc + bias.
// ---------------------------------------------------------------------------
__global__ __launch_bounds__(256) void gemm_mma(
    const float* __restrict__ A, const float* __restrict__ Bt,
    const float* __restrict__ bias, float* __restrict__ C,
    int M, int N, int K, int mode)
{
    __shared__ float As[128][36];
    __shared__ float Bs[128][36];

    const int tid  = threadIdx.x;
    const int wid  = tid >> 5;
    const int lane = tid & 31;
    const int g    = lane >> 2;
    const int t    = lane & 3;
    const int wm   = wid & 3;
    const int wn   = wid >> 2;
    const int m0 = blockIdx.y * 128;
    const int n0 = blockIdx.x * 128;

    const int lr = tid >> 3;
    const int lk = (tid & 7) * 4;

    float c[2][8][4];
#pragma unroll
    for (int mt = 0; mt < 2; ++mt)
#pragma unroll
        for (int nt = 0; nt < 8; ++nt)
#pragma unroll
            for (int j = 0; j < 4; ++j) c[mt][nt][j] = 0.f;

    for (int k0 = 0; k0 < K; k0 += 32) {
#pragma unroll
        for (int i = 0; i < 4; ++i) {
            int r = lr + i * 32;
            float4 av = *(const float4*)(A + (size_t)(m0 + r) * K + k0 + lk);
            float4 bv = *(const float4*)(Bt + (size_t)(n0 + r) * K + k0 + lk);
            float4 ac, bc;
            ac.x = __uint_as_float(f2tf32(av.x)); ac.y = __uint_as_float(f2tf32(av.y));
            ac.z = __uint_as_float(f2tf32(av.z)); ac.w = __uint_as_float(f2tf32(av.w));
            bc.x = __uint_as_float(f2tf32(bv.x)); bc.y = __uint_as_float(f2tf32(bv.y));
            bc.z = __uint_as_float(f2tf32(bv.z)); bc.w = __uint_as_float(f2tf32(bv.w));
            *(float4*)&As[r][lk] = ac;
            *(float4*)&Bs[r][lk] = bc;
        }
        __syncthreads();

#pragma unroll
        for (int kt = 0; kt < 4; ++kt) {
            const int kb = kt * 8;
            uint32_t bf[8][2];
#pragma unroll
            for (int nt = 0; nt < 8; ++nt) {
                int n = wn * 64 + nt * 8 + g;
                bf[nt][0] = __float_as_uint(Bs[n][kb + t]);
                bf[nt][1] = __float_as_uint(Bs[n][kb + t + 4]);
            }
#pragma unroll
            for (int mt = 0; mt < 2; ++mt) {
                int mb = wm * 32 + mt * 16;
                uint32_t a0 = __float_as_uint(As[mb + g][kb + t]);
                uint32_t a1 = __float_as_uint(As[mb + g + 8][kb + t]);
                uint32_t a2 = __float_as_uint(As[mb + g][kb + t + 4]);
                uint32_t a3 = __float_as_uint(As[mb + g + 8][kb + t + 4]);
#pragma unroll
                for (int nt = 0; nt < 8; ++nt)
                    mma_tf32(c[mt][nt][0], c[mt][nt][1], c[mt][nt][2], c[mt][nt][3],
                             a0, a1, a2, a3, bf[nt][0], bf[nt][1]);
            }
        }
        __syncthreads();
    }

    const int nbase = n0 + wn * 64;
    if (mode == 0) {
        const int which = nbase >> 10;
        const int h = (nbase & 1023) >> 6;
#pragma unroll
        for (int mt = 0; mt < 2; ++mt) {
            int r0 = m0 + wm * 32 + mt * 16 + g;
            int bb0 = r0 >> 11, tt0 = r0 & (TSEQ - 1);
            int r1 = r0 + 8;
            int bb1 = r1 >> 11, tt1 = r1 & (TSEQ - 1);
            if (which == 2) {
                // V: [B,H,D,T] transposed store (scalar 4B scatters)
                float* base0 = g_v + ((size_t)(bb0 * NHEAD + h)) * HSIZE * TSEQ;
                float* base1 = g_v + ((size_t)(bb1 * NHEAD + h)) * HSIZE * TSEQ;
#pragma unroll
                for (int nt = 0; nt < 8; ++nt) {
                    int d = nt * 8 + 2 * t;
                    base0[(size_t)d * TSEQ + tt0]       = c[mt][nt][0];
                    base0[(size_t)(d + 1) * TSEQ + tt0] = c[mt][nt][1];
                    base1[(size_t)d * TSEQ + tt1]       = c[mt][nt][2];
                    base1[(size_t)(d + 1) * TSEQ + tt1] = c[mt][nt][3];
                }
            } else {
                const float sc = (which == 0) ? 0.125f : 1.0f;
                float* base = (which == 0) ? g_q : g_k;
                float* d0 = base + (((size_t)(bb0 * NHEAD + h) * TSEQ) + tt0) * HSIZE;
                float* d1 = base + (((size_t)(bb1 * NHEAD + h) * TSEQ) + tt1) * HSIZE;
#pragma unroll
                for (int nt = 0; nt < 8; ++nt) {
                    int d = nt * 8 + 2 * t;
                    float2 v0 = {c[mt][nt][0] * sc, c[mt][nt][1] * sc};
                    float2 v1 = {c[mt][nt][2] * sc, c[mt][nt][3] * sc};
                    *(float2*)(d0 + d) = v0;
                    *(float2*)(d1 + d) = v1;
                }
            }
        }
    } else {
#pragma unroll
        for (int mt = 0; mt < 2; ++mt) {
            int r0 = m0 + wm * 32 + mt * 16 + g;
#pragma unroll
            for (int nt = 0; nt < 8; ++nt) {
                int n = nbase + nt * 8 + 2 * t;
                float2 bv = *(const float2*)(bias + n);
                float2 v0 = {c[mt][nt][0] + bv.x, c[mt][nt][1] + bv.y};
                float2 v1 = {c[mt][nt][2] + bv.x, c[mt][nt][3] + bv.y};
                *(float2*)(C + (size_t)r0 * N + n) = v0;
                *(float2*)(C + (size_t)(r0 + 8) * N + n) = v1;
            }
        }
    }
}

// ---------------------------------------------------------------------------
// Tensor-core causal flash attention (tf32 mma.sync).
// CTA: 128 queries of one (b,h). 8 warps x 16 query rows each (warp-local
// softmax). K tile [64x68], V^T tile [64x68] in smem; Q frags in registers;
// P via warp-private smem (aliases Q staging buffer). Pad 68 -> bank 4g+t,
// conflict-free fragment LDS. grid=(16,64) with qb reversed for balance.
// Dyn smem = (128+64+64)*68*4 = 69632 B.
// ---------------------------------------------------------------------------
#define PAD 68
__global__ __launch_bounds__(256) void attn_mma()
{
    extern __shared__ float sm[];
    float* Qs = sm;                  // [128][PAD], aliased by Ps after Q->regs
    float* Ks = sm + 128 * PAD;      // [64][PAD]   keys x dim
    float* Vs = Ks + 64 * PAD;       // [64][PAD]   dim x keys (V^T)
    float* Ps = Qs;

    const int tid  = threadIdx.x;
    const int wid  = tid >> 5;
    const int lane = tid & 31;
    const int g    = lane >> 2;
    const int t    = lane & 3;
    const int mb   = wid * 16;       // warp's query-row base in tile
    const int bh   = blockIdx.y;
    const int qb   = gridDim.x - 1 - blockIdx.x;
    const int q0   = qb * 128;

    // stage Q tile [128][64] -> smem (tf32-rounded), coalesced
    const float* Qg = g_q + ((size_t)bh * TSEQ + q0) * HSIZE;
#pragma unroll
    for (int i = 0; i < 8; ++i) {
        int f = tid + i * 256;           // 2048 float4
        int r = f >> 4, c4 = (f & 15) * 4;
        float4 v = *(const float4*)(Qg + (size_t)r * HSIZE + c4);
        v.x = __uint_as_float(f2tf32(v.x)); v.y = __uint_as_float(f2tf32(v.y));
        v.z = __uint_as_float(f2tf32(v.z)); v.w = __uint_as_float(f2tf32(v.w));
        *(float4*)&Qs[r * PAD + c4] = v;
    }
    __syncthreads();

    // Q fragments -> registers (8 k-chunks x 4 regs)
    uint32_t qa[8][4];
#pragma unroll
    for (int kb = 0; kb < 8; ++kb) {
        qa[kb][0] = __float_as_uint(Qs[(mb + g) * PAD + kb * 8 + t]);
        qa[kb][1] = __float_as_uint(Qs[(mb + g + 8) * PAD + kb * 8 + t]);
        qa[kb][2] = __float_as_uint(Qs[(mb + g) * PAD + kb * 8 + t + 4]);
        qa[kb][3] = __float_as_uint(Qs[(mb + g + 8) * PAD + kb * 8 + t + 4]);
    }

    float o[8][4];
#pragma unroll
    for (int nt = 0; nt < 8; ++nt)
#pragma unroll
        for (int j = 0; j < 4; ++j) o[nt][j] = 0.f;
    float m0 = -INFINITY, m1 = -INFINITY, l0 = 0.f, l1 = 0.f;

    const int row0 = q0 + mb + g;
    const int row1 = row0 + 8;
    const int ntiles = qb * 2 + 2;

    const float* Kg = g_k + (size_t)bh * TSEQ * HSIZE;
    const float* Vg = g_v + (size_t)bh * HSIZE * TSEQ;

    for (int kt = 0; kt < ntiles; ++kt) {
        __syncthreads();   // protect K/V smem reuse
        // K tile: [64 keys][64 dim]; V^T tile: [64 dim][64 keys]
#pragma unroll
        for (int i = 0; i < 4; ++i) {
            int f = tid + i * 256;       // 1024 float4 each
            int r = f >> 4, c4 = (f & 15) * 4;
            float4 kv = *(const float4*)(Kg + (size_t)(kt * 64 + r) * HSIZE + c4);
            kv.x = __uint_as_float(f2tf32(kv.x)); kv.y = __uint_as_float(f2tf32(kv.y));
            kv.z = __uint_as_float(f2tf32(kv.z)); kv.w = __uint_as_float(f2tf32(kv.w));
            *(float4*)&Ks[r * PAD + c4] = kv;
            float4 vv = *(const float4*)(Vg + (size_t)r * TSEQ + kt * 64 + c4);
            vv.x = __uint_as_float(f2tf32(vv.x)); vv.y = __uint_as_float(f2tf32(vv.y));
            vv.z = __uint_as_float(f2tf32(vv.z)); vv.w = __uint_as_float(f2tf32(vv.w));
            *(float4*)&Vs[r * PAD + c4] = vv;
        }
        __syncthreads();

        // S = Q K^T  (16 rows x 64 keys per warp)
        float s[8][4];
#pragma unroll
        for (int nt = 0; nt < 8; ++nt)
#pragma unroll
            for (int j = 0; j < 4; ++j) s[nt][j] = 0.f;
#pragma unroll
        for (int kb = 0; kb < 8; ++kb) {
#pragma unroll
            for (int nt = 0; nt < 8; ++nt) {
                int n = nt * 8 + g;
                uint32_t b0 = __float_as_uint(Ks[n * PAD + kb * 8 + t]);
                uint32_t b1 = __float_as_uint(Ks[n * PAD + kb * 8 + t + 4]);
                mma_tf32(s[nt][0], s[nt][1], s[nt][2], s[nt][3],
                         qa[kb][0], qa[kb][1], qa[kb][2], qa[kb][3], b0, b1);
            }
        }

        // causal mask on diagonal tiles
        if (kt >= qb * 2) {
#pragma unroll
            for (int nt = 0; nt < 8; ++nt) {
                int col = kt * 64 + nt * 8 + 2 * t;
                if (col > row0)     s[nt][0] = -INFINITY;
                if (col + 1 > row0) s[nt][1] = -INFINITY;
                if (col > row1)     s[nt][2] = -INFINITY;
                if (col + 1 > row1) s[nt][3] = -INFINITY;
            }
        }

        // online softmax (rows row0, row1)
        float mx0 = -INFINITY, mx1 = -INFINITY;
#pragma unroll
        for (int nt = 0; nt < 8; ++nt) {
            mx0 = fmaxf(mx0, fmaxf(s[nt][0], s[nt][1]));
            mx1 = fmaxf(mx1, fmaxf(s[nt][2], s[nt][3]));
        }
        mx0 = fmaxf(mx0, __shfl_xor_sync(0xffffffffu, mx0, 1));
        mx0 = fmaxf(mx0, __shfl_xor_sync(0xffffffffu, mx0, 2));
        mx1 = fmaxf(mx1, __shfl_xor_sync(0xffffffffu, mx1, 1));
        mx1 = fmaxf(mx1, __shfl_xor_sync(0xffffffffu, mx1, 2));
        float nm0 = fmaxf(m0, mx0), nm1 = fmaxf(m1, mx1);
        float cr0 = __expf(m0 - nm0), cr1 = __expf(m1 - nm1);
        l0 *= cr0; l1 *= cr1;
#pragma unroll
        for (int nt = 0; nt < 8; ++nt) {
            o[nt][0] *= cr0; o[nt][1] *= cr0;
            o[nt][2] *= cr1; o[nt][3] *= cr1;
        }
        float s0 = 0.f, s1 = 0.f;
#pragma unroll
        for (int nt = 0; nt < 8; ++nt) {
            float p00 = __expf(s[nt][0] - nm0);
            float p01 = __expf(s[nt][1] - nm0);
            float p10 = __expf(s[nt][2] - nm1);
            float p11 = __expf(s[nt][3] - nm1);
            s0 += p00 + p01; s1 += p10 + p11;
            float2 w0 = {__uint_as_float(f2tf32(p00)), __uint_as_float(f2tf32(p01))};
            float2 w1 = {__uint_as_float(f2tf32(p10)), __uint_as_float(f2tf32(p11))};
            *(float2*)&Ps[(mb + g) * PAD + nt * 8 + 2 * t] = w0;
            *(float2*)&Ps[(mb + g + 8) * PAD + nt * 8 + 2 * t] = w1;
        }
        s0 += __shfl_xor_sync(0xffffffffu, s0, 1);
        s0 += __shfl_xor_sync(0xffffffffu, s0, 2);
        s1 += __shfl_xor_sync(0xffffffffu, s1, 1);
        s1 += __shfl_xor_sync(0xffffffffu, s1, 2);
        l0 += s0; l1 += s1;
        m0 = nm0; m1 = nm1;
        __syncwarp();

        // O += P V  (A = P from warp-private smem, B = V^T tile)
#pragma unroll
        for (int kb = 0; kb < 8; ++kb) {
            uint32_t pa0 = __float_as_uint(Ps[(mb + g) * PAD + kb * 8 + t]);
            uint32_t pa1 = __float_as_uint(Ps[(mb + g + 8) * PAD + kb * 8 + t]);
            uint32_t pa2 = __float_as_uint(Ps[(mb + g) * PAD + kb * 8 + t + 4]);
            uint32_t pa3 = __float_as_uint(Ps[(mb + g + 8) * PAD + kb * 8 + t + 4]);
#pragma unroll
            for (int nt = 0; nt < 8; ++nt) {
                int n = nt * 8 + g;
                uint32_t b0 = __float_as_uint(Vs[n * PAD + kb * 8 + t]);
                uint32_t b1 = __float_as_uint(Vs[n * PAD + kb * 8 + t + 4]);
                mma_tf32(o[nt][0], o[nt][1], o[nt][2], o[nt][3],
                         pa0, pa1, pa2, pa3, b0, b1);
            }
        }
        __syncwarp();   // Ps reuse next tile
    }

    // write O / l -> g_attn [B*T, C]
    const int b = bh >> 4, h = bh & 15;
    const float inv0 = 1.f / l0, inv1 = 1.f / l1;
    float* O0 = g_attn + ((size_t)(b * TSEQ) + row0) * CEMB + h * HSIZE;
    float* O1 = g_attn + ((size_t)(b * TSEQ) + row1) * CEMB + h * HSIZE;
#pragma unroll
    for (int nt = 0; nt < 8; ++nt) {
        int d = nt * 8 + 2 * t;
        float2 v0 = {o[nt][0] * inv0, o[nt][1] * inv0};
        float2 v1 = {o[nt][2] * inv1, o[nt][3] * inv1};
        *(float2*)(O0 + d) = v0;
        *(float2*)(O1 + d) = v1;
    }
}

// ---------------------------------------------------------------------------
extern "C" void kernel_launch(void* const* d_in, const int* in_sizes, int n_in,
                              void* d_out, int out_size)
{
    const float* x      = (const float*)d_in[0];   // [B,T,C]
    const float* w_qkv  = (const float*)d_in[1];   // [C, 3C]
    const float* w_proj = (const float*)d_in[2];   // [C, C]
    const float* b_proj = (const float*)d_in[3];   // [C]
    float* out = (float*)d_out;                    // [B,T,C]

    float *attn_ptr = nullptr, *wtq = nullptr, *wtp = nullptr;
    cudaGetSymbolAddress((void**)&attn_ptr, g_attn);
    cudaGetSymbolAddress((void**)&wtq, g_wt_qkv);
    cudaGetSymbolAddress((void**)&wtp, g_wt_proj);

    const int ATTN_SMEM = (128 + 64 + 64) * PAD * 4;   // 69632
    cudaFuncSetAttribute(attn_mma, cudaFuncAttributeMaxDynamicSharedMemorySize, ATTN_SMEM);

    // 0) transpose weights to K-major
    transpose_k<<<dim3(3 * CEMB / 32, CEMB / 32), dim3(32, 8)>>>(w_qkv, wtq, CEMB, 3 * CEMB);
    transpose_k<<<dim3(CEMB / 32, CEMB / 32), dim3(32, 8)>>>(w_proj, wtp, CEMB, CEMB);

    // 1) QKV GEMM (tf32 mma) + head-major scatter (V transposed)
    gemm_mma<<<dim3(3 * CEMB / 128, MROWS / 128), 256>>>(
        x, wtq, nullptr, nullptr, MROWS, 3 * CEMB, CEMB, 0);

    // 2) Causal flash attention (tf32 mma)
    attn_mma<<<dim3(TSEQ / 128, BATCH * NHEAD), 256, ATTN_SMEM>>>();

    // 3) Output projection + bias (tf32 mma)
    gemm_mma<<<dim3(CEMB / 128, MROWS / 128), 256>>>(
        attn_ptr, wtp, b_proj, out, MROWS, CEMB, CEMB, 1);
}